// round 15
// baseline (speedup 1.0000x reference)
#include <cuda_runtime.h>
#include <cuda_bf16.h>
#include <stdint.h>
#include <math.h>

#define V_NUM 6890
#define B_NUM 512
#define J_NUM 24
#define NBETA 10
#define KP    207   // (J-1)*9
#define VC    (V_NUM*3)   // 20670
#define KPAD  256         // 207 pose + pad + 10 shape + 2 vt(double-bf16) + pad
#define KTS   32          // k per stage
#define NSTG  8
#define NTHR  256
#define KSH   224         // k-offset of the shape/vt extension

typedef unsigned long long ull;
typedef unsigned int u32;

__constant__ int c_par[24] = {-1,0,0,0,1,2,3,4,5,6,7,8,9,9,9,12,13,14,16,17,18,19,20,21};

// Scratch (no allocations allowed)
__device__ float g_Jt0[J_NUM*3];
__device__ float g_JS[J_NUM*3*NBETA];
// A4 layout: [pg(64)][j(24)][r(3)][pl(4)][8 floats: (r0,r1,r2,t3) pair-interleaved]
__device__ __align__(128) float g_A4[64*24*3*4*8];
__device__ __align__(16) __nv_bfloat16 g_pfB[B_NUM*KPAD];      // A: [b][k] = pose_feature | betas | 1,1
__device__ __align__(16) __nv_bfloat16 g_pdB[(size_t)VC*KPAD]; // B: [n][k] = posedirs^T | shapedirs | vt_hi,vt_lo

// ---- packed f32x2 helpers -------------------------------------------------
__device__ __forceinline__ ull pk(float l, float h) {
    ull r; asm("mov.b64 %0, {%1, %2};" : "=l"(r) : "f"(l), "f"(h)); return r;
}
__device__ __forceinline__ float ulo(ull v) {
    float l, h; asm("mov.b64 {%0, %1}, %2;" : "=f"(l), "=f"(h) : "l"(v)); return l;
}
__device__ __forceinline__ float uhi(ull v) {
    float l, h; asm("mov.b64 {%0, %1}, %2;" : "=f"(l), "=f"(h) : "l"(v)); return h;
}
__device__ __forceinline__ ull ffma2(ull a, ull b, ull c) {
    ull r; asm("fma.rn.f32x2 %0, %1, %2, %3;" : "=l"(r) : "l"(a), "l"(b), "l"(c)); return r;
}

// ---- cp.async helpers -----------------------------------------------------
__device__ __forceinline__ void cp16(u32 dst, const void* src) {
    asm volatile("cp.async.ca.shared.global [%0], [%1], 16;" :: "r"(dst), "l"(src));
}
__device__ __forceinline__ void cp4(u32 dst, const void* src) {
    asm volatile("cp.async.ca.shared.global [%0], [%1], 4;" :: "r"(dst), "l"(src));
}
__device__ __forceinline__ void cp_commit() { asm volatile("cp.async.commit_group;"); }
template<int N> __device__ __forceinline__ void cp_wait() {
    asm volatile("cp.async.wait_group %0;" :: "n"(N));
}

// ---- ldmatrix + bf16 mma ----------------------------------------------------
__device__ __forceinline__ void ldsm4(u32& r0, u32& r1, u32& r2, u32& r3, u32 addr) {
    asm volatile("ldmatrix.sync.aligned.m8n8.x4.shared.b16 {%0,%1,%2,%3}, [%4];"
        : "=r"(r0), "=r"(r1), "=r"(r2), "=r"(r3) : "r"(addr));
}
__device__ __forceinline__ void mma_bf16(float* d, const u32* a, u32 b0, u32 b1) {
    asm volatile(
        "mma.sync.aligned.m16n8k16.row.col.f32.bf16.bf16.f32 "
        "{%0,%1,%2,%3}, {%4,%5,%6,%7}, {%8,%9}, {%0,%1,%2,%3};"
        : "+f"(d[0]), "+f"(d[1]), "+f"(d[2]), "+f"(d[3])
        : "r"(a[0]), "r"(a[1]), "r"(a[2]), "r"(a[3]), "r"(b0), "r"(b1));
}

// ---------------------------------------------------------------------------
// cvtB_k: build the extended B matrix (same as R14).
// ---------------------------------------------------------------------------
__global__ void cvtB_k(const float* __restrict__ pdirs,
                       const float* __restrict__ vt,
                       const float* __restrict__ sd)
{
    __shared__ float tile[32][33];
    int t = threadIdx.x;   // 256
    if (blockIdx.x == 0 && blockIdx.y == 0) {
        if (t < J_NUM*3) g_Jt0[t] = 0.0f;
        for (int i = t; i < J_NUM*30; i += 256) g_JS[i] = 0.0f;
    }
    int n0 = blockIdx.x * 32;
    int k0 = blockIdx.y * 32;

    if (k0 == KSH) {
        int nn2 = t >> 3, q = t & 7;
        int n = n0 + nn2;
        if (n < VC) {
            int v = n / 3, c = n % 3;
            float vtv = vt[n];
            __nv_bfloat16 hi = __float2bfloat16(vtv);
            float lo = vtv - __bfloat162float(hi);
            __nv_bfloat16 vals[4];
#pragma unroll
            for (int i = 0; i < 4; i++) {
                int kk = q*4 + i;
                float x = 0.0f;
                if (kk < NBETA)      x = sd[v*30 + c*10 + kk];
                vals[i] = __float2bfloat16(x);
                if (kk == 10) vals[i] = hi;
                if (kk == 11) vals[i] = __float2bfloat16(lo);
            }
            __nv_bfloat162* dst = (__nv_bfloat162*)&g_pdB[(size_t)n*KPAD + k0 + q*4];
            dst[0] = __nv_bfloat162{vals[0], vals[1]};
            dst[1] = __nv_bfloat162{vals[2], vals[3]};
        }
        return;
    }

    int nn = t & 31, kq = t >> 5;
#pragma unroll
    for (int i = 0; i < 4; i++) {
        int kk = kq + i*8;
        int k = k0 + kk, n = n0 + nn;
        tile[kk][nn] = (k < KP && n < VC) ? pdirs[(size_t)k*VC + n] : 0.0f;
    }
    __syncthreads();
    int nn2 = t >> 3, q = t & 7;
    int n = n0 + nn2;
    if (n < VC) {
        __nv_bfloat162 p01 = __floats2bfloat162_rn(tile[q*4+0][nn2], tile[q*4+1][nn2]);
        __nv_bfloat162 p23 = __floats2bfloat162_rn(tile[q*4+2][nn2], tile[q*4+3][nn2]);
        __nv_bfloat162* dst = (__nv_bfloat162*)&g_pdB[(size_t)n*KPAD + k0 + q*4];
        dst[0] = p01;
        dst[1] = p23;
    }
}

// ---------------------------------------------------------------------------
__global__ void regress_k(const float* __restrict__ Jreg,
                          const float* __restrict__ vt,
                          const float* __restrict__ sd)
{
    int j = blockIdx.x;
    int chunk = blockIdx.y;
    const int CH = (V_NUM + 13) / 14;
    int v0 = chunk * CH;
    int v1 = min(v0 + CH, V_NUM);
    int t = threadIdx.x;
    int lane = t & 31, w = t >> 5;

    float acc[33];
#pragma unroll
    for (int i = 0; i < 33; i++) acc[i] = 0.f;
    for (int v = v0 + t; v < v1; v += 256) {
        float r = Jreg[j*V_NUM + v];
#pragma unroll
        for (int c = 0; c < 3; c++) acc[c] += r * vt[v*3+c];
#pragma unroll
        for (int i = 0; i < 30; i++) acc[3+i] += r * sd[v*30+i];
    }
    __shared__ float red[8][33];
#pragma unroll
    for (int i = 0; i < 33; i++) {
        float v = acc[i];
#pragma unroll
        for (int o = 16; o; o >>= 1) v += __shfl_xor_sync(0xffffffffu, v, o);
        if (lane == 0) red[w][i] = v;
    }
    __syncthreads();
    if (t < 33) {
        float s = 0.f;
#pragma unroll
        for (int ww = 0; ww < 8; ww++) s += red[ww][t];
        if (t < 3) atomicAdd(&g_Jt0[j*3 + t], s);
        else       atomicAdd(&g_JS[j*30 + (t-3)], s);
    }
}

// ---------------------------------------------------------------------------
// pose_k: 8 batches per block; extended A row; A4 warp-contiguous layout.
// ---------------------------------------------------------------------------
__global__ void pose_k(const float* __restrict__ pose,
                       const float* __restrict__ betas,
                       const float* __restrict__ trans)
{
    int warp = threadIdx.x >> 5;
    int lane = threadIdx.x & 31;
    int b = blockIdx.x*8 + warp;
    __shared__ float R[8][24][9];
    __shared__ float Jt[8][24][3];
    __shared__ float Tl[8][24][12];
    __shared__ float Tw[8][24][12];

    if (lane < 24) {
        float rx = pose[b*72 + lane*3 + 0];
        float ry = pose[b*72 + lane*3 + 1];
        float rz = pose[b*72 + lane*3 + 2];
        float ang = sqrtf(rx*rx + ry*ry + rz*rz + 1e-16f);
        float inv = 1.0f/ang;
        float ax = rx*inv, ay = ry*inv, az = rz*inv;
        float s = sinf(ang), c = cosf(ang), tt = 1.0f - c;
        R[warp][lane][0] = c + tt*ax*ax;    R[warp][lane][1] = tt*ax*ay - s*az; R[warp][lane][2] = tt*ax*az + s*ay;
        R[warp][lane][3] = tt*ax*ay + s*az; R[warp][lane][4] = c + tt*ay*ay;    R[warp][lane][5] = tt*ay*az - s*ax;
        R[warp][lane][6] = tt*ax*az - s*ay; R[warp][lane][7] = tt*ay*az + s*ax; R[warp][lane][8] = c + tt*az*az;

        float bet[NBETA];
#pragma unroll
        for (int k = 0; k < NBETA; k++) bet[k] = betas[b*NBETA + k];
#pragma unroll
        for (int c3 = 0; c3 < 3; c3++) {
            float a = g_Jt0[lane*3 + c3];
#pragma unroll
            for (int k = 0; k < NBETA; k++) a += g_JS[lane*30 + c3*10 + k] * bet[k];
            Jt[warp][lane][c3] = a;
        }
    }
    __syncwarp();

    // extended A row: pf | betas | 1,1
    for (int idx = lane; idx < KPAD; idx += 32) {
        float v = 0.0f;
        if (idx < KP) {
            int j = idx/9 + 1, e = idx%9;
            v = R[warp][j][e] - ((e == 0 || e == 4 || e == 8) ? 1.0f : 0.0f);
        } else if (idx >= KSH && idx < KSH + NBETA) {
            v = betas[b*NBETA + (idx - KSH)];
        } else if (idx == KSH + 10 || idx == KSH + 11) {
            v = 1.0f;
        }
        g_pfB[b*KPAD + idx] = __float2bfloat16(v);
    }

    if (lane < 24) {
        float tx, ty, tz;
        if (lane == 0) { tx = Jt[warp][0][0]; ty = Jt[warp][0][1]; tz = Jt[warp][0][2]; }
        else {
            int p = c_par[lane];
            tx = Jt[warp][lane][0] - Jt[warp][p][0];
            ty = Jt[warp][lane][1] - Jt[warp][p][1];
            tz = Jt[warp][lane][2] - Jt[warp][p][2];
        }
        Tl[warp][lane][0] = R[warp][lane][0]; Tl[warp][lane][1] = R[warp][lane][1]; Tl[warp][lane][2]  = R[warp][lane][2]; Tl[warp][lane][3]  = tx;
        Tl[warp][lane][4] = R[warp][lane][3]; Tl[warp][lane][5] = R[warp][lane][4]; Tl[warp][lane][6]  = R[warp][lane][5]; Tl[warp][lane][7]  = ty;
        Tl[warp][lane][8] = R[warp][lane][6]; Tl[warp][lane][9] = R[warp][lane][7]; Tl[warp][lane][10] = R[warp][lane][8]; Tl[warp][lane][11] = tz;
    }
    __syncwarp();
    if (lane < 12) Tw[warp][0][lane] = Tl[warp][0][lane];
    __syncwarp();
    for (int i = 1; i < 24; i++) {
        if (lane < 12) {
            int r = lane >> 2, cc = lane & 3;
            int p = c_par[i];
            float v = Tw[warp][p][r*4+0]*Tl[warp][i][0+cc] + Tw[warp][p][r*4+1]*Tl[warp][i][4+cc] + Tw[warp][p][r*4+2]*Tl[warp][i][8+cc];
            if (cc == 3) v += Tw[warp][p][r*4+3];
            Tw[warp][i][lane] = v;
        }
        __syncwarp();
    }
    if (lane < 24) {
        float jx = Jt[warp][lane][0], jy = Jt[warp][lane][1], jz = Jt[warp][lane][2];
        int pg = b >> 3;          // pair-group of 4 pairs = 8 batches
        int pl = (b >> 1) & 3;    // pair within group
        int s  = b & 1;           // batch within pair
#pragma unroll
        for (int r = 0; r < 3; r++) {
            float r0 = Tw[warp][lane][r*4+0], r1 = Tw[warp][lane][r*4+1], r2 = Tw[warp][lane][r*4+2];
            float t3 = Tw[warp][lane][r*4+3] - (r0*jx + r1*jy + r2*jz) + trans[b*3+r];
            size_t base = ((((size_t)pg*24 + lane)*3 + r)*4 + pl)*8 + s;
            g_A4[base + 0] = r0;
            g_A4[base + 2] = r1;
            g_A4[base + 4] = r2;
            g_A4[base + 6] = t3;
        }
    }
}

// ---------------------------------------------------------------------------
// Main kernel: extended bf16 GEMM (v_posed in one shot) + FFMA2 skinning.
// ---------------------------------------------------------------------------
#define AS_B   (64*80)
#define BS_B   (96*80)
#define AS0b   0
#define BS0b   (3*AS_B)           // 15360
#define STG_ENDb (BS0b + 3*BS_B)  // 38400 B = 9600 floats
#define VP_OFF 0                  // aliased: Vp [64][100] = 25600 B
#define W_OFF  9600
#define SMEM_F (W_OFF + 24*32)    // 10368 floats = 41472 B

__global__ void __launch_bounds__(NTHR, 3) lbs_k(
    const float* __restrict__ wts,
    float* __restrict__ out)
{
    __shared__ __align__(16) float smem[SMEM_F];
    u32 sbase = (u32)__cvta_generic_to_shared(smem);

    int t = threadIdx.x;
    int vb = blockIdx.x * 32;
    int n0 = blockIdx.x * 96;
    int b0 = blockIdx.y * 64;
    bool tailv = (vb + 32 > V_NUM);

    // ---- group 0: weights + stage 0 ----
    for (int idx = t; idx < 24*32; idx += NTHR) {
        int j = idx >> 5, vv = idx & 31;
        int v = vb + vv;
        cp4(sbase + (W_OFF + idx)*4, (v < V_NUM) ? &wts[v*24 + j] : wts);
    }

    auto fill = [&](int buf, int kc) {
        u32 adst = sbase + AS0b + buf*AS_B;
        const __nv_bfloat16* asrc = g_pfB + (size_t)b0*KPAD + kc;
        for (int idx = t; idx < 256; idx += NTHR) {
            int b = idx >> 2, q = idx & 3;
            cp16(adst + b*80 + q*16, asrc + (size_t)b*KPAD + q*8);
        }
        u32 bdst = sbase + BS0b + buf*BS_B;
        for (int idx = t; idx < 384; idx += NTHR) {
            int n = idx >> 2, q = idx & 3;
            int gn = n0 + n;
            const __nv_bfloat16* s = g_pdB + (size_t)(gn < VC ? gn : 0)*KPAD + kc;
            cp16(bdst + n*80 + q*16, s + q*8);
        }
    };

    fill(0, 0);        cp_commit();
    fill(1, KTS);      cp_commit();

    // ---- GEMM: 8 stages x 2 k-steps, ldmatrix + m16n8k16 bf16 ----
    int wid = t >> 5, lane = t & 31;
    int wm = wid & 3;
    int wn = wid >> 2;
    int gid = lane >> 2, tg = lane & 3;

    u32 a_lane_off = (u32)((wm*16 + (lane & 15))*80 + (lane >> 4)*16);
    u32 b_lane_off = (u32)((wn*48 + (lane >> 4)*8 + (lane & 7))*80 + ((lane >> 3) & 1)*16);

    float d[6][4];
#pragma unroll
    for (int f = 0; f < 6; f++)
#pragma unroll
        for (int r = 0; r < 4; r++) d[f][r] = 0.0f;

#pragma unroll 1
    for (int it = 0; it < NSTG; it++) {
        cp_wait<1>();
        __syncthreads();

        int buf = it % 3;
        u32 abase = sbase + AS0b + buf*AS_B + a_lane_off;
        u32 bbase = sbase + BS0b + buf*BS_B + b_lane_off;
#pragma unroll
        for (int ks = 0; ks < 2; ks++) {
            u32 a[4];
            ldsm4(a[0], a[1], a[2], a[3], abase + ks*32);
            u32 b[12];
#pragma unroll
            for (int fp = 0; fp < 3; fp++)
                ldsm4(b[fp*4+0], b[fp*4+1], b[fp*4+2], b[fp*4+3],
                      bbase + fp*16*80 + ks*32);
#pragma unroll
            for (int f = 0; f < 6; f++)
                mma_bf16(d[f], a, b[2*f], b[2*f+1]);
        }

        if (it + 2 < NSTG) fill((it + 2) % 3, (it + 2)*KTS);
        cp_commit();
    }
    __syncthreads();   // all compute done before Vp aliases the stage buffers

    // ---- epilogue: D fragments -> Vp[64][100] (= full v_posed) ----
    {
        float* Vp = smem + VP_OFF;
        int rb = wm*16 + gid;
#pragma unroll
        for (int f = 0; f < 6; f++) {
            int col = wn*48 + f*8 + 2*tg;
            *(float2*)&Vp[rb*100 + col]     = make_float2(d[f][0], d[f][1]);
            *(float2*)&Vp[(rb+8)*100 + col] = make_float2(d[f][2], d[f][3]);
        }
    }
    __syncthreads();

    // ---- phase 2 mapping ----
    int vg = t & 7;            // 8 vert-groups of 4 verts
    int bg = t >> 3;           // 32 batch-pairs; bg = wid*4 + (lane>>3)
    int pl = lane >> 3;        // pair within the warp's group

    // pack v_posed over batch pair
    ull xp[12];
    {
        const float* VL = &smem[VP_OFF + (bg*2)*100 + vg*12];
        const float* VH = VL + 100;
        float4 L0 = *(const float4*)&VL[0], L1 = *(const float4*)&VL[4], L2 = *(const float4*)&VL[8];
        float4 H0 = *(const float4*)&VH[0], H1 = *(const float4*)&VH[4], H2 = *(const float4*)&VH[8];
        float L[12] = {L0.x,L0.y,L0.z,L0.w, L1.x,L1.y,L1.z,L1.w, L2.x,L2.y,L2.z,L2.w};
        float H[12] = {H0.x,H0.y,H0.z,H0.w, H1.x,H1.y,H1.z,H1.w, H2.x,H2.y,H2.z,H2.w};
#pragma unroll
        for (int e = 0; e < 12; e++)
            xp[e] = pk(L[e], H[e]);
    }

    // ---- skinning blend; A4 warp-contiguous (1 line per warp-load) ----
    ull o2[12];
#pragma unroll
    for (int e = 0; e < 12; e++) o2[e] = pk(0.f, 0.f);

    // pg = (b0/2 + bg) >> 2 = b0/8 + wid  (warp-uniform)
    const float* A4 = g_A4 + (((size_t)(b0 >> 3) + wid)*24)*3*4*8;

#pragma unroll 2
    for (int j = 0; j < 24; j++) {
        float4 w4 = *(const float4*)&smem[W_OFF + j*32 + vg*4];
        ull wp[4] = { pk(w4.x,w4.x), pk(w4.y,w4.y), pk(w4.z,w4.z), pk(w4.w,w4.w) };
#pragma unroll
        for (int r = 0; r < 3; r++) {
            const ulonglong2* Ar = (const ulonglong2*)(A4 + ((j*3 + r)*4 + pl)*8);
            ulonglong2 Ar0 = Ar[0], Ar1 = Ar[1];
            ull a0 = Ar0.x, a1 = Ar0.y, a2 = Ar1.x, a3 = Ar1.y;
#pragma unroll
            for (int dv = 0; dv < 4; dv++) {
                ull q = ffma2(a0, xp[dv*3+0],
                        ffma2(a1, xp[dv*3+1],
                        ffma2(a2, xp[dv*3+2], a3)));
                o2[dv*3+r] = ffma2(wp[dv], q, o2[dv*3+r]);
            }
        }
    }

    // ---- store: 6 x STG.64 per batch ----
    int v0 = vb + vg*4;
    if (!tailv) {
#pragma unroll
        for (int s = 0; s < 2; s++) {
            int b = b0 + bg*2 + s;
            float* o = out + ((size_t)b*V_NUM + v0)*3;
#pragma unroll
            for (int k = 0; k < 6; k++) {
                float2 v2;
                v2.x = s ? uhi(o2[2*k])   : ulo(o2[2*k]);
                v2.y = s ? uhi(o2[2*k+1]) : ulo(o2[2*k+1]);
                *(float2*)(o + 2*k) = v2;
            }
        }
    } else {
#pragma unroll
        for (int s = 0; s < 2; s++) {
            int b = b0 + bg*2 + s;
#pragma unroll
            for (int e = 0; e < 12; e++) {
                int v = v0 + e/3;
                if (v < V_NUM) {
                    float val = s ? uhi(o2[e]) : ulo(o2[e]);
                    out[((size_t)b*V_NUM + v)*3 + (e % 3)] = val;
                }
            }
        }
    }
}

extern "C" void kernel_launch(void* const* d_in, const int* in_sizes, int n_in,
                              void* d_out, int out_size)
{
    const float* pose   = (const float*)d_in[0];
    const float* betas  = (const float*)d_in[1];
    const float* trans  = (const float*)d_in[2];
    const float* vt     = (const float*)d_in[3];
    const float* sd     = (const float*)d_in[4];
    const float* pdirs  = (const float*)d_in[5];
    const float* Jreg   = (const float*)d_in[6];
    const float* wts    = (const float*)d_in[7];
    // d_in[8] = parents (fixed SMPL topology, baked into __constant__)

    cvtB_k<<<dim3((VC + 31)/32, KPAD/32), 256>>>(pdirs, vt, sd);   // 646 x 8
    regress_k<<<dim3(24, 14), 256>>>(Jreg, vt, sd);
    pose_k<<<B_NUM/8, 256>>>(pose, betas, trans);
    dim3 grid((VC + 95)/96, B_NUM/64);   // 216 x 8
    lbs_k<<<grid, NTHR>>>(wts, (float*)d_out);
}

// round 16
// speedup vs baseline: 1.5190x; 1.5190x over previous
#include <cuda_runtime.h>
#include <cuda_bf16.h>
#include <stdint.h>
#include <math.h>

#define V_NUM 6890
#define B_NUM 512
#define J_NUM 24
#define NBETA 10
#define KP    207   // (J-1)*9
#define VC    (V_NUM*3)   // 20670
#define KPAD  256         // 207 pose + pad + 10 shape + 2 vt(double-bf16) + pad
#define KTS   32          // k per stage
#define NSTG  8
#define NTHR  256
#define KSH   224         // k-offset of the shape/vt extension

typedef unsigned long long ull;
typedef unsigned int u32;

__constant__ int c_par[24] = {-1,0,0,0,1,2,3,4,5,6,7,8,9,9,9,12,13,14,16,17,18,19,20,21};

// Scratch (no allocations allowed)
__device__ float g_Jt0[J_NUM*3];
__device__ float g_JS[J_NUM*3*NBETA];
__device__ __align__(16) float g_A2[(B_NUM/2)*580];            // batch-pair-interleaved affines
__device__ __align__(16) __nv_bfloat16 g_pfB[B_NUM*KPAD];      // A: [b][k] = pose_feature | betas | 1,1
__device__ __align__(16) __nv_bfloat16 g_pdB[(size_t)VC*KPAD]; // B: [n][k] = posedirs^T | shapedirs | vt_hi,vt_lo

// ---- packed f32x2 helpers -------------------------------------------------
__device__ __forceinline__ ull pk(float l, float h) {
    ull r; asm("mov.b64 %0, {%1, %2};" : "=l"(r) : "f"(l), "f"(h)); return r;
}
__device__ __forceinline__ float ulo(ull v) {
    float l, h; asm("mov.b64 {%0, %1}, %2;" : "=f"(l), "=f"(h) : "l"(v)); return l;
}
__device__ __forceinline__ float uhi(ull v) {
    float l, h; asm("mov.b64 {%0, %1}, %2;" : "=f"(l), "=f"(h) : "l"(v)); return h;
}
__device__ __forceinline__ ull ffma2(ull a, ull b, ull c) {
    ull r; asm("fma.rn.f32x2 %0, %1, %2, %3;" : "=l"(r) : "l"(a), "l"(b), "l"(c)); return r;
}

// ---- cp.async helpers -----------------------------------------------------
__device__ __forceinline__ void cp16(u32 dst, const void* src) {
    asm volatile("cp.async.ca.shared.global [%0], [%1], 16;" :: "r"(dst), "l"(src));
}
__device__ __forceinline__ void cp4(u32 dst, const void* src) {
    asm volatile("cp.async.ca.shared.global [%0], [%1], 4;" :: "r"(dst), "l"(src));
}
__device__ __forceinline__ void cp_commit() { asm volatile("cp.async.commit_group;"); }
template<int N> __device__ __forceinline__ void cp_wait() {
    asm volatile("cp.async.wait_group %0;" :: "n"(N));
}

// ---- ldmatrix + bf16 mma ----------------------------------------------------
__device__ __forceinline__ void ldsm4(u32& r0, u32& r1, u32& r2, u32& r3, u32 addr) {
    asm volatile("ldmatrix.sync.aligned.m8n8.x4.shared.b16 {%0,%1,%2,%3}, [%4];"
        : "=r"(r0), "=r"(r1), "=r"(r2), "=r"(r3) : "r"(addr));
}
__device__ __forceinline__ void mma_bf16(float* d, const u32* a, u32 b0, u32 b1) {
    asm volatile(
        "mma.sync.aligned.m16n8k16.row.col.f32.bf16.bf16.f32 "
        "{%0,%1,%2,%3}, {%4,%5,%6,%7}, {%8,%9}, {%0,%1,%2,%3};"
        : "+f"(d[0]), "+f"(d[1]), "+f"(d[2]), "+f"(d[3])
        : "r"(a[0]), "r"(a[1]), "r"(a[2]), "r"(a[3]), "r"(b0), "r"(b1));
}

// ---------------------------------------------------------------------------
// cvtB_k: build the extended B matrix.
// ---------------------------------------------------------------------------
__global__ void cvtB_k(const float* __restrict__ pdirs,
                       const float* __restrict__ vt,
                       const float* __restrict__ sd)
{
    __shared__ float tile[32][33];
    int t = threadIdx.x;   // 256
    if (blockIdx.x == 0 && blockIdx.y == 0) {
        if (t < J_NUM*3) g_Jt0[t] = 0.0f;
        for (int i = t; i < J_NUM*30; i += 256) g_JS[i] = 0.0f;
    }
    int n0 = blockIdx.x * 32;
    int k0 = blockIdx.y * 32;

    if (k0 == KSH) {
        int nn2 = t >> 3, q = t & 7;
        int n = n0 + nn2;
        if (n < VC) {
            int v = n / 3, c = n % 3;
            float vtv = vt[n];
            __nv_bfloat16 hi = __float2bfloat16(vtv);
            float lo = vtv - __bfloat162float(hi);
            __nv_bfloat16 vals[4];
#pragma unroll
            for (int i = 0; i < 4; i++) {
                int kk = q*4 + i;
                float x = 0.0f;
                if (kk < NBETA)      x = sd[v*30 + c*10 + kk];
                vals[i] = __float2bfloat16(x);
                if (kk == 10) vals[i] = hi;
                if (kk == 11) vals[i] = __float2bfloat16(lo);
            }
            __nv_bfloat162* dst = (__nv_bfloat162*)&g_pdB[(size_t)n*KPAD + k0 + q*4];
            dst[0] = __nv_bfloat162{vals[0], vals[1]};
            dst[1] = __nv_bfloat162{vals[2], vals[3]};
        }
        return;
    }

    int nn = t & 31, kq = t >> 5;
#pragma unroll
    for (int i = 0; i < 4; i++) {
        int kk = kq + i*8;
        int k = k0 + kk, n = n0 + nn;
        tile[kk][nn] = (k < KP && n < VC) ? pdirs[(size_t)k*VC + n] : 0.0f;
    }
    __syncthreads();
    int nn2 = t >> 3, q = t & 7;
    int n = n0 + nn2;
    if (n < VC) {
        __nv_bfloat162 p01 = __floats2bfloat162_rn(tile[q*4+0][nn2], tile[q*4+1][nn2]);
        __nv_bfloat162 p23 = __floats2bfloat162_rn(tile[q*4+2][nn2], tile[q*4+3][nn2]);
        __nv_bfloat162* dst = (__nv_bfloat162*)&g_pdB[(size_t)n*KPAD + k0 + q*4];
        dst[0] = p01;
        dst[1] = p23;
    }
}

// ---------------------------------------------------------------------------
__global__ void regress_k(const float* __restrict__ Jreg,
                          const float* __restrict__ vt,
                          const float* __restrict__ sd)
{
    int j = blockIdx.x;
    int chunk = blockIdx.y;
    const int CH = (V_NUM + 13) / 14;
    int v0 = chunk * CH;
    int v1 = min(v0 + CH, V_NUM);
    int t = threadIdx.x;
    int lane = t & 31, w = t >> 5;

    float acc[33];
#pragma unroll
    for (int i = 0; i < 33; i++) acc[i] = 0.f;
    for (int v = v0 + t; v < v1; v += 256) {
        float r = Jreg[j*V_NUM + v];
#pragma unroll
        for (int c = 0; c < 3; c++) acc[c] += r * vt[v*3+c];
#pragma unroll
        for (int i = 0; i < 30; i++) acc[3+i] += r * sd[v*30+i];
    }
    __shared__ float red[8][33];
#pragma unroll
    for (int i = 0; i < 33; i++) {
        float v = acc[i];
#pragma unroll
        for (int o = 16; o; o >>= 1) v += __shfl_xor_sync(0xffffffffu, v, o);
        if (lane == 0) red[w][i] = v;
    }
    __syncthreads();
    if (t < 33) {
        float s = 0.f;
#pragma unroll
        for (int ww = 0; ww < 8; ww++) s += red[ww][t];
        if (t < 3) atomicAdd(&g_Jt0[j*3 + t], s);
        else       atomicAdd(&g_JS[j*30 + (t-3)], s);
    }
}

// ---------------------------------------------------------------------------
// pose_k: 8 batches per block; extended A row: pf | betas | 1,1.
// ---------------------------------------------------------------------------
__global__ void pose_k(const float* __restrict__ pose,
                       const float* __restrict__ betas,
                       const float* __restrict__ trans)
{
    int warp = threadIdx.x >> 5;
    int lane = threadIdx.x & 31;
    int b = blockIdx.x*8 + warp;
    __shared__ float R[8][24][9];
    __shared__ float Jt[8][24][3];
    __shared__ float Tl[8][24][12];
    __shared__ float Tw[8][24][12];

    if (lane < 24) {
        float rx = pose[b*72 + lane*3 + 0];
        float ry = pose[b*72 + lane*3 + 1];
        float rz = pose[b*72 + lane*3 + 2];
        float ang = sqrtf(rx*rx + ry*ry + rz*rz + 1e-16f);
        float inv = 1.0f/ang;
        float ax = rx*inv, ay = ry*inv, az = rz*inv;
        float s = sinf(ang), c = cosf(ang), tt = 1.0f - c;
        R[warp][lane][0] = c + tt*ax*ax;    R[warp][lane][1] = tt*ax*ay - s*az; R[warp][lane][2] = tt*ax*az + s*ay;
        R[warp][lane][3] = tt*ax*ay + s*az; R[warp][lane][4] = c + tt*ay*ay;    R[warp][lane][5] = tt*ay*az - s*ax;
        R[warp][lane][6] = tt*ax*az - s*ay; R[warp][lane][7] = tt*ay*az + s*ax; R[warp][lane][8] = c + tt*az*az;

        float bet[NBETA];
#pragma unroll
        for (int k = 0; k < NBETA; k++) bet[k] = betas[b*NBETA + k];
#pragma unroll
        for (int c3 = 0; c3 < 3; c3++) {
            float a = g_Jt0[lane*3 + c3];
#pragma unroll
            for (int k = 0; k < NBETA; k++) a += g_JS[lane*30 + c3*10 + k] * bet[k];
            Jt[warp][lane][c3] = a;
        }
    }
    __syncwarp();

    // extended A row: pf | betas | 1,1
    for (int idx = lane; idx < KPAD; idx += 32) {
        float v = 0.0f;
        if (idx < KP) {
            int j = idx/9 + 1, e = idx%9;
            v = R[warp][j][e] - ((e == 0 || e == 4 || e == 8) ? 1.0f : 0.0f);
        } else if (idx >= KSH && idx < KSH + NBETA) {
            v = betas[b*NBETA + (idx - KSH)];
        } else if (idx == KSH + 10 || idx == KSH + 11) {
            v = 1.0f;
        }
        g_pfB[b*KPAD + idx] = __float2bfloat16(v);
    }

    if (lane < 24) {
        float tx, ty, tz;
        if (lane == 0) { tx = Jt[warp][0][0]; ty = Jt[warp][0][1]; tz = Jt[warp][0][2]; }
        else {
            int p = c_par[lane];
            tx = Jt[warp][lane][0] - Jt[warp][p][0];
            ty = Jt[warp][lane][1] - Jt[warp][p][1];
            tz = Jt[warp][lane][2] - Jt[warp][p][2];
        }
        Tl[warp][lane][0] = R[warp][lane][0]; Tl[warp][lane][1] = R[warp][lane][1]; Tl[warp][lane][2]  = R[warp][lane][2]; Tl[warp][lane][3]  = tx;
        Tl[warp][lane][4] = R[warp][lane][3]; Tl[warp][lane][5] = R[warp][lane][4]; Tl[warp][lane][6]  = R[warp][lane][5]; Tl[warp][lane][7]  = ty;
        Tl[warp][lane][8] = R[warp][lane][6]; Tl[warp][lane][9] = R[warp][lane][7]; Tl[warp][lane][10] = R[warp][lane][8]; Tl[warp][lane][11] = tz;
    }
    __syncwarp();
    if (lane < 12) Tw[warp][0][lane] = Tl[warp][0][lane];
    __syncwarp();
    for (int i = 1; i < 24; i++) {
        if (lane < 12) {
            int r = lane >> 2, cc = lane & 3;
            int p = c_par[i];
            float v = Tw[warp][p][r*4+0]*Tl[warp][i][0+cc] + Tw[warp][p][r*4+1]*Tl[warp][i][4+cc] + Tw[warp][p][r*4+2]*Tl[warp][i][8+cc];
            if (cc == 3) v += Tw[warp][p][r*4+3];
            Tw[warp][i][lane] = v;
        }
        __syncwarp();
    }
    if (lane < 24) {
        float jx = Jt[warp][lane][0], jy = Jt[warp][lane][1], jz = Jt[warp][lane][2];
        size_t base = (size_t)(b >> 1) * 580 + (b & 1);
#pragma unroll
        for (int r = 0; r < 3; r++) {
            float r0 = Tw[warp][lane][r*4+0], r1 = Tw[warp][lane][r*4+1], r2 = Tw[warp][lane][r*4+2];
            float t3 = Tw[warp][lane][r*4+3] - (r0*jx + r1*jy + r2*jz) + trans[b*3+r];
            int e = lane*12 + r*4;
            g_A2[base + (e+0)*2] = r0;
            g_A2[base + (e+1)*2] = r1;
            g_A2[base + (e+2)*2] = r2;
            g_A2[base + (e+3)*2] = t3;
        }
    }
}

// ---------------------------------------------------------------------------
// Main kernel: extended bf16 GEMM (v_posed in one shot) + FFMA2 skinning.
// ---------------------------------------------------------------------------
#define AS_B   (64*80)
#define BS_B   (96*80)
#define AS0b   0
#define BS0b   (3*AS_B)           // 15360
#define STG_ENDb (BS0b + 3*BS_B)  // 38400 B = 9600 floats
#define VP_OFF 0                  // aliased: Vp [64][100] = 25600 B
#define W_OFF  9600
#define SMEM_F (W_OFF + 24*32)    // 10368 floats = 41472 B

__global__ void __launch_bounds__(NTHR, 3) lbs_k(
    const float* __restrict__ wts,
    float* __restrict__ out)
{
    __shared__ __align__(16) float smem[SMEM_F];
    u32 sbase = (u32)__cvta_generic_to_shared(smem);

    int t = threadIdx.x;
    int vb = blockIdx.x * 32;
    int n0 = blockIdx.x * 96;
    int b0 = blockIdx.y * 64;
    bool tailv = (vb + 32 > V_NUM);

    // ---- group 0: weights + stage 0 ----
    for (int idx = t; idx < 24*32; idx += NTHR) {
        int j = idx >> 5, vv = idx & 31;
        int v = vb + vv;
        cp4(sbase + (W_OFF + idx)*4, (v < V_NUM) ? &wts[v*24 + j] : wts);
    }

    auto fill = [&](int buf, int kc) {
        u32 adst = sbase + AS0b + buf*AS_B;
        const __nv_bfloat16* asrc = g_pfB + (size_t)b0*KPAD + kc;
        for (int idx = t; idx < 256; idx += NTHR) {
            int b = idx >> 2, q = idx & 3;
            cp16(adst + b*80 + q*16, asrc + (size_t)b*KPAD + q*8);
        }
        u32 bdst = sbase + BS0b + buf*BS_B;
        for (int idx = t; idx < 384; idx += NTHR) {
            int n = idx >> 2, q = idx & 3;
            int gn = n0 + n;
            const __nv_bfloat16* s = g_pdB + (size_t)(gn < VC ? gn : 0)*KPAD + kc;
            cp16(bdst + n*80 + q*16, s + q*8);
        }
    };

    fill(0, 0);        cp_commit();
    fill(1, KTS);      cp_commit();

    // ---- GEMM: 8 stages x 2 k-steps, ldmatrix + m16n8k16 bf16 ----
    int wid = t >> 5, lane = t & 31;
    int wm = wid & 3;
    int wn = wid >> 2;
    int gid = lane >> 2, tg = lane & 3;

    u32 a_lane_off = (u32)((wm*16 + (lane & 15))*80 + (lane >> 4)*16);
    u32 b_lane_off = (u32)((wn*48 + (lane >> 4)*8 + (lane & 7))*80 + ((lane >> 3) & 1)*16);

    float d[6][4];
#pragma unroll
    for (int f = 0; f < 6; f++)
#pragma unroll
        for (int r = 0; r < 4; r++) d[f][r] = 0.0f;

#pragma unroll 1
    for (int it = 0; it < NSTG; it++) {
        cp_wait<1>();
        __syncthreads();

        int buf = it % 3;
        u32 abase = sbase + AS0b + buf*AS_B + a_lane_off;
        u32 bbase = sbase + BS0b + buf*BS_B + b_lane_off;
#pragma unroll
        for (int ks = 0; ks < 2; ks++) {
            u32 a[4];
            ldsm4(a[0], a[1], a[2], a[3], abase + ks*32);
            u32 b[12];
#pragma unroll
            for (int fp = 0; fp < 3; fp++)
                ldsm4(b[fp*4+0], b[fp*4+1], b[fp*4+2], b[fp*4+3],
                      bbase + fp*16*80 + ks*32);
#pragma unroll
            for (int f = 0; f < 6; f++)
                mma_bf16(d[f], a, b[2*f], b[2*f+1]);
        }

        if (it + 2 < NSTG) fill((it + 2) % 3, (it + 2)*KTS);
        cp_commit();
    }
    __syncthreads();   // all compute done before Vp aliases the stage buffers

    // ---- epilogue: D fragments -> Vp[64][100] (= full v_posed) ----
    {
        float* Vp = smem + VP_OFF;
        int rb = wm*16 + gid;
#pragma unroll
        for (int f = 0; f < 6; f++) {
            int col = wn*48 + f*8 + 2*tg;
            *(float2*)&Vp[rb*100 + col]     = make_float2(d[f][0], d[f][1]);
            *(float2*)&Vp[(rb+8)*100 + col] = make_float2(d[f][2], d[f][3]);
        }
    }
    __syncthreads();

    // ---- phase 2 mapping ----
    int vg = t & 7;            // 8 vert-groups of 4 verts
    int bg = t >> 3;           // 32 batch-pairs

    // pack v_posed over batch pair
    ull xp[12];
    {
        const float* VL = &smem[VP_OFF + (bg*2)*100 + vg*12];
        const float* VH = VL + 100;
        float4 L0 = *(const float4*)&VL[0], L1 = *(const float4*)&VL[4], L2 = *(const float4*)&VL[8];
        float4 H0 = *(const float4*)&VH[0], H1 = *(const float4*)&VH[4], H2 = *(const float4*)&VH[8];
        float L[12] = {L0.x,L0.y,L0.z,L0.w, L1.x,L1.y,L1.z,L1.w, L2.x,L2.y,L2.z,L2.w};
        float H[12] = {H0.x,H0.y,H0.z,H0.w, H1.x,H1.y,H1.z,H1.w, H2.x,H2.y,H2.z,H2.w};
#pragma unroll
        for (int e = 0; e < 12; e++)
            xp[e] = pk(L[e], H[e]);
    }

    // ---- skinning blend (A from L2-resident gmem) ----
    ull o2[12];
#pragma unroll
    for (int e = 0; e < 12; e++) o2[e] = pk(0.f, 0.f);

    const ulonglong2* Ab = (const ulonglong2*)(g_A2 + ((size_t)(b0 >> 1) + bg)*580);

#pragma unroll 2
    for (int j = 0; j < 24; j++) {
        float4 w4 = *(const float4*)&smem[W_OFF + j*32 + vg*4];
        ull wp[4] = { pk(w4.x,w4.x), pk(w4.y,w4.y), pk(w4.z,w4.z), pk(w4.w,w4.w) };
#pragma unroll
        for (int r = 0; r < 3; r++) {
            ulonglong2 Ar0 = Ab[j*6 + r*2], Ar1 = Ab[j*6 + r*2 + 1];
            ull a0 = Ar0.x, a1 = Ar0.y, a2 = Ar1.x, a3 = Ar1.y;
#pragma unroll
            for (int dv = 0; dv < 4; dv++) {
                ull q = ffma2(a0, xp[dv*3+0],
                        ffma2(a1, xp[dv*3+1],
                        ffma2(a2, xp[dv*3+2], a3)));
                o2[dv*3+r] = ffma2(wp[dv], q, o2[dv*3+r]);
            }
        }
    }

    // ---- store: 6 x STG.64 per batch ----
    int v0 = vb + vg*4;
    if (!tailv) {
#pragma unroll
        for (int s = 0; s < 2; s++) {
            int b = b0 + bg*2 + s;
            float* o = out + ((size_t)b*V_NUM + v0)*3;
#pragma unroll
            for (int k = 0; k < 6; k++) {
                float2 v2;
                v2.x = s ? uhi(o2[2*k])   : ulo(o2[2*k]);
                v2.y = s ? uhi(o2[2*k+1]) : ulo(o2[2*k+1]);
                *(float2*)(o + 2*k) = v2;
            }
        }
    } else {
#pragma unroll
        for (int s = 0; s < 2; s++) {
            int b = b0 + bg*2 + s;
#pragma unroll
            for (int e = 0; e < 12; e++) {
                int v = v0 + e/3;
                if (v < V_NUM) {
                    float val = s ? uhi(o2[e]) : ulo(o2[e]);
                    out[((size_t)b*V_NUM + v)*3 + (e % 3)] = val;
                }
            }
        }
    }
}

extern "C" void kernel_launch(void* const* d_in, const int* in_sizes, int n_in,
                              void* d_out, int out_size)
{
    const float* pose   = (const float*)d_in[0];
    const float* betas  = (const float*)d_in[1];
    const float* trans  = (const float*)d_in[2];
    const float* vt     = (const float*)d_in[3];
    const float* sd     = (const float*)d_in[4];
    const float* pdirs  = (const float*)d_in[5];
    const float* Jreg   = (const float*)d_in[6];
    const float* wts    = (const float*)d_in[7];
    // d_in[8] = parents (fixed SMPL topology, baked into __constant__)

    cvtB_k<<<dim3((VC + 31)/32, KPAD/32), 256>>>(pdirs, vt, sd);   // 646 x 8
    regress_k<<<dim3(24, 14), 256>>>(Jreg, vt, sd);
    pose_k<<<B_NUM/8, 256>>>(pose, betas, trans);
    dim3 grid((VC + 95)/96, B_NUM/64);   // 216 x 8
    lbs_k<<<grid, NTHR>>>(wts, (float*)d_out);
}